// round 1
// baseline (speedup 1.0000x reference)
#include <cuda_runtime.h>
#include <math.h>

// Problem constants
#define B_   8
#define N_   8192
#define C_   384
#define H_   8
#define D_   48
#define M_   (B_ * N_)      // 65536 rows
#define QKVC (3 * C_)       // 1152

// Scratch (static device arrays — no dynamic allocation allowed)
// qkvT layout: [which(3)][b(8)][h(8)][d(48)][n(8192)]  => rows = 9216
__device__ float g_qkvT[9216L * N_];
// y layout: [b][h][d][n] => rows = 3072
__device__ float g_y[3072L * N_];
// 1/max(norm,eps): rows 0..3071 = q, 3072..6143 = k
__device__ float g_rn[6144];
// Gram partials: [chunk(8)][bh(64)][d*48+e]
__device__ float g_Spart[8 * 64 * 2304];
// softmaxed attention, TRANSPOSED: [bh][e][d]
__device__ float g_attnT[64 * 2304];

// ---------------------------------------------------------------------------
// K1: qkv = x @ Wqkv^T, scatter-transposed epilogue into g_qkvT
// C[m][c] = sum_k x[m][k] * w[c][k]; 64x64 tile, BK=16, 256 thr, 4x4 microtile
// ---------------------------------------------------------------------------
__global__ void k_qkv_gemm(const float* __restrict__ x, const float* __restrict__ w)
{
    __shared__ float As[16][64];
    __shared__ float Bs[16][64];
    const int tid = threadIdx.x;
    const int tx = tid & 15, ty = tid >> 4;
    const int row0 = blockIdx.y * 64;
    const int col0 = blockIdx.x * 64;

    float acc[4][4] = {};

    const int lr = tid >> 2;          // 0..63
    const int lk = (tid & 3) * 4;     // 0,4,8,12
    const float* xa = x + (size_t)(row0 + lr) * C_ + lk;
    const float* wb = w + (size_t)(col0 + lr) * C_ + lk;

    for (int k0 = 0; k0 < C_; k0 += 16) {
        float4 a4 = *(const float4*)(xa + k0);
        float4 b4 = *(const float4*)(wb + k0);
        As[lk + 0][lr] = a4.x; As[lk + 1][lr] = a4.y;
        As[lk + 2][lr] = a4.z; As[lk + 3][lr] = a4.w;
        Bs[lk + 0][lr] = b4.x; Bs[lk + 1][lr] = b4.y;
        Bs[lk + 2][lr] = b4.z; Bs[lk + 3][lr] = b4.w;
        __syncthreads();
#pragma unroll
        for (int kk = 0; kk < 16; kk++) {
            float4 av = *(const float4*)&As[kk][ty * 4];
            float4 bv = *(const float4*)&Bs[kk][tx * 4];
            acc[0][0] += av.x * bv.x; acc[0][1] += av.x * bv.y;
            acc[0][2] += av.x * bv.z; acc[0][3] += av.x * bv.w;
            acc[1][0] += av.y * bv.x; acc[1][1] += av.y * bv.y;
            acc[1][2] += av.y * bv.z; acc[1][3] += av.y * bv.w;
            acc[2][0] += av.z * bv.x; acc[2][1] += av.z * bv.y;
            acc[2][2] += av.z * bv.z; acc[2][3] += av.z * bv.w;
            acc[3][0] += av.w * bv.x; acc[3][1] += av.w * bv.y;
            acc[3][2] += av.w * bv.z; acc[3][3] += av.w * bv.w;
        }
        __syncthreads();
    }

    // Epilogue: col c -> which = c/384, cc = c%384 (= h*48+d).
    // qkvT flat row = which*3072 + b*384 + cc. 4 consecutive n per thread -> float4.
    const int b = row0 >> 13;                 // tile never crosses b (64 | 8192)
    const int nbase = (row0 & (N_ - 1)) + ty * 4;
#pragma unroll
    for (int j = 0; j < 4; j++) {
        int c = col0 + tx * 4 + j;
        int which = c / C_;
        int cc = c - which * C_;
        size_t off = ((size_t)(which * 3072 + b * C_ + cc)) * N_ + nbase;
        float4 v = make_float4(acc[0][j], acc[1][j], acc[2][j], acc[3][j]);
        *(float4*)(g_qkvT + off) = v;
    }
}

// ---------------------------------------------------------------------------
// K2a: reciprocal L2 norms of q and k rows (6144 rows of 8192)
// ---------------------------------------------------------------------------
__global__ void k_norms()
{
    const int idx = blockIdx.x;               // 0..6143
    const float4* row = (const float4*)(g_qkvT + (size_t)idx * N_);
    float s = 0.f;
    for (int i = threadIdx.x; i < N_ / 4; i += 256) {
        float4 v = row[i];
        s += v.x * v.x + v.y * v.y + v.z * v.z + v.w * v.w;
    }
    __shared__ float red[256];
    red[threadIdx.x] = s;
    __syncthreads();
    for (int off = 128; off > 0; off >>= 1) {
        if (threadIdx.x < off) red[threadIdx.x] += red[threadIdx.x + off];
        __syncthreads();
    }
    if (threadIdx.x == 0)
        g_rn[idx] = 1.0f / fmaxf(sqrtf(red[0]), 1e-12f);
}

// ---------------------------------------------------------------------------
// K2b: raw Gram partials  Spart[chunk][bh][d][e] = sum_{n in chunk} q[d,n]k[e,n]
// grid (8 chunks, 64 bh), 256 threads, 3x3 microtile over the 48x48 output
// ---------------------------------------------------------------------------
__global__ void k_logits()
{
    const int chunk = blockIdx.x;     // 0..7 (1024 n each)
    const int bh    = blockIdx.y;     // 0..63
    const int tid   = threadIdx.x;
    __shared__ float Qs[32][49];
    __shared__ float Ks[32][49];

    const int td = (tid >> 4) * 3;    // 0..45
    const int te = (tid & 15) * 3;    // 0..45
    float acc[3][3] = {};

    const size_t qbase = (size_t)(bh * 48) * N_ + (size_t)chunk * 1024;
    const size_t kbase = qbase + (size_t)3072 * N_;

    for (int t = 0; t < 1024; t += 32) {
#pragma unroll
        for (int it = 0; it < 3; it++) {
            int id  = tid + it * 256;        // 0..767
            int isK = (id >= 384);
            int lid = id - isK * 384;        // 0..383
            int d = lid >> 3;
            int nseg = (lid & 7) * 4;
            size_t base = isK ? kbase : qbase;
            float4 v = *(const float4*)(g_qkvT + base + (size_t)d * N_ + t + nseg);
            float (*S)[49] = isK ? Ks : Qs;
            S[nseg + 0][d] = v.x; S[nseg + 1][d] = v.y;
            S[nseg + 2][d] = v.z; S[nseg + 3][d] = v.w;
        }
        __syncthreads();
#pragma unroll
        for (int kk = 0; kk < 32; kk++) {
            float q0 = Qs[kk][td], q1 = Qs[kk][td + 1], q2 = Qs[kk][td + 2];
            float p0 = Ks[kk][te], p1 = Ks[kk][te + 1], p2 = Ks[kk][te + 2];
            acc[0][0] += q0 * p0; acc[0][1] += q0 * p1; acc[0][2] += q0 * p2;
            acc[1][0] += q1 * p0; acc[1][1] += q1 * p1; acc[1][2] += q1 * p2;
            acc[2][0] += q2 * p0; acc[2][1] += q2 * p1; acc[2][2] += q2 * p2;
        }
        __syncthreads();
    }

    float* outp = g_Spart + ((size_t)chunk * 64 + bh) * 2304;
#pragma unroll
    for (int i = 0; i < 3; i++)
#pragma unroll
        for (int j = 0; j < 3; j++)
            outp[(td + i) * 48 + (te + j)] = acc[i][j];
}

// ---------------------------------------------------------------------------
// K2c: sum partials, apply norm scaling, softmax over e, write transposed attn
// grid 64 (bh), 48 threads; thread d owns a softmax row
// ---------------------------------------------------------------------------
__global__ void k_softmax()
{
    const int bh = blockIdx.x;
    const int d  = threadIdx.x;
    if (d >= 48) return;
    const float rq = g_rn[bh * 48 + d];
    const float* rk = g_rn + 3072 + bh * 48;

    float vals[48];
    float mx = -1e30f;
#pragma unroll
    for (int e = 0; e < 48; e++) {
        float s = 0.f;
#pragma unroll
        for (int c = 0; c < 8; c++)
            s += g_Spart[((size_t)c * 64 + bh) * 2304 + d * 48 + e];
        float v = s * rq * rk[e];
        vals[e] = v;
        mx = fmaxf(mx, v);
    }
    float sum = 0.f;
#pragma unroll
    for (int e = 0; e < 48; e++) {
        vals[e] = expf(vals[e] - mx);
        sum += vals[e];
    }
    float inv = 1.0f / sum;
#pragma unroll
    for (int e = 0; e < 48; e++)
        g_attnT[(size_t)bh * 2304 + e * 48 + d] = vals[e] * inv;
}

// ---------------------------------------------------------------------------
// K2d: y[b,h,d,n] = sum_e attn[d,e] * v[e,n]
// grid (32 n-chunks, 64 bh), 256 thr; thread owns column n, acc[48] in regs
// ---------------------------------------------------------------------------
__global__ void k_av()
{
    const int chunk = blockIdx.x;     // 0..31 (256 n each)
    const int bh    = blockIdx.y;
    const int tid   = threadIdx.x;
    __shared__ __align__(16) float At[2304];   // At[e*48 + d]
#pragma unroll
    for (int i = 0; i < 9; i++)
        At[tid + i * 256] = g_attnT[(size_t)bh * 2304 + tid + i * 256];
    __syncthreads();

    const int n = chunk * 256 + tid;
    const size_t vbase = ((size_t)(2 * 3072 + bh * 48)) * N_ + n;
    float acc[48] = {};
#pragma unroll 4
    for (int e = 0; e < 48; e++) {
        float vv = g_qkvT[vbase + (size_t)e * N_];
        const float4* arow = (const float4*)&At[e * 48];
#pragma unroll
        for (int d4 = 0; d4 < 12; d4++) {
            float4 a = arow[d4];
            acc[d4 * 4 + 0] += a.x * vv;
            acc[d4 * 4 + 1] += a.y * vv;
            acc[d4 * 4 + 2] += a.z * vv;
            acc[d4 * 4 + 3] += a.w * vv;
        }
    }
    const size_t ybase = (size_t)(bh * 48) * N_ + n;
#pragma unroll
    for (int d = 0; d < 48; d++)
        g_y[ybase + (size_t)d * N_] = acc[d];
}

// ---------------------------------------------------------------------------
// K3: out[b,n,c] = sum_j y[b, j/48, j%48, n] * w_proj[c][j] + b_proj[c]
// same SGEMM shape as K1 but A is gathered (n-contiguous) from g_y
// ---------------------------------------------------------------------------
__global__ void k_proj_gemm(const float* __restrict__ wp,
                            const float* __restrict__ bp,
                            float* __restrict__ out)
{
    __shared__ float As[16][64];   // As[j_local][m_local]
    __shared__ float Bs[16][64];   // Bs[k_local][c_local]
    const int tid = threadIdx.x;
    const int tx = tid & 15, ty = tid >> 4;
    const int row0 = blockIdx.y * 64;
    const int col0 = blockIdx.x * 64;
    const int b  = row0 >> 13;
    const int n0 = row0 & (N_ - 1);

    float acc[4][4] = {};

    const int jl  = tid >> 4;          // 0..15
    const int seg = (tid & 15) * 4;    // 0..60
    const int lr  = tid >> 2;
    const int lk  = (tid & 3) * 4;
    const float* wrow = wp + (size_t)(col0 + lr) * C_ + lk;

    for (int k0 = 0; k0 < C_; k0 += 16) {
        int j = k0 + jl;  // feature index = h*48+d, matches g_y row b*384+j
        float4 a4 = *(const float4*)(g_y + ((size_t)(b * C_ + j)) * N_ + n0 + seg);
        *(float4*)&As[jl][seg] = a4;
        float4 b4 = *(const float4*)(wrow + k0);
        Bs[lk + 0][lr] = b4.x; Bs[lk + 1][lr] = b4.y;
        Bs[lk + 2][lr] = b4.z; Bs[lk + 3][lr] = b4.w;
        __syncthreads();
#pragma unroll
        for (int kk = 0; kk < 16; kk++) {
            float4 av = *(const float4*)&As[kk][ty * 4];
            float4 bv = *(const float4*)&Bs[kk][tx * 4];
            acc[0][0] += av.x * bv.x; acc[0][1] += av.x * bv.y;
            acc[0][2] += av.x * bv.z; acc[0][3] += av.x * bv.w;
            acc[1][0] += av.y * bv.x; acc[1][1] += av.y * bv.y;
            acc[1][2] += av.y * bv.z; acc[1][3] += av.y * bv.w;
            acc[2][0] += av.z * bv.x; acc[2][1] += av.z * bv.y;
            acc[2][2] += av.z * bv.z; acc[2][3] += av.z * bv.w;
            acc[3][0] += av.w * bv.x; acc[3][1] += av.w * bv.y;
            acc[3][2] += av.w * bv.z; acc[3][3] += av.w * bv.w;
        }
        __syncthreads();
    }

    const int c = col0 + tx * 4;
    float4 bias = *(const float4*)(bp + c);
#pragma unroll
    for (int i = 0; i < 4; i++) {
        int m = row0 + ty * 4 + i;
        float4 v = make_float4(acc[i][0] + bias.x, acc[i][1] + bias.y,
                               acc[i][2] + bias.z, acc[i][3] + bias.w);
        *(float4*)(out + (size_t)m * C_ + c) = v;
    }
}

// ---------------------------------------------------------------------------
extern "C" void kernel_launch(void* const* d_in, const int* in_sizes, int n_in,
                              void* d_out, int out_size)
{
    const float* x      = (const float*)d_in[0];
    const float* w_qkv  = (const float*)d_in[1];
    const float* w_proj = (const float*)d_in[2];
    const float* b_proj = (const float*)d_in[3];
    float* out = (float*)d_out;

    dim3 g1(QKVC / 64, M_ / 64);          // 18 x 1024
    k_qkv_gemm<<<g1, 256>>>(x, w_qkv);

    k_norms<<<6144, 256>>>();

    dim3 g2(8, 64);
    k_logits<<<g2, 256>>>();

    k_softmax<<<64, 48>>>();

    dim3 g3(32, 64);
    k_av<<<g3, 256>>>();

    dim3 g4(C_ / 64, M_ / 64);            // 6 x 1024
    k_proj_gemm<<<g4, 256>>>(w_proj, b_proj, out);
}

// round 2
// speedup vs baseline: 1.2184x; 1.2184x over previous
#include <cuda_runtime.h>
#include <math.h>

// Problem constants
#define B_   8
#define N_   8192
#define C_   384
#define H_   8
#define D_   48
#define M_   (B_ * N_)      // 65536 rows
#define QKVC (3 * C_)       // 1152

typedef unsigned long long u64;

// Scratch (static device arrays)
__device__ float g_qkvT[9216L * N_];   // [which(3)][b][h][d][n]
__device__ float g_y[3072L * N_];      // [b][h][d][n]
__device__ float g_rn[6144];           // 1/max(norm,eps): q rows then k rows
__device__ float g_Spart[8 * 64 * 2304];
__device__ float g_attnT[64 * 2304];   // [bh][e][d]

// ---- packed f32x2 helpers -------------------------------------------------
__device__ __forceinline__ u64 pk2(float a, float b) {
    u64 r; asm("mov.b64 %0, {%1,%2};" : "=l"(r) : "f"(a), "f"(b)); return r;
}
__device__ __forceinline__ float2 upk(u64 v) {
    float2 r; asm("mov.b64 {%0,%1}, %2;" : "=f"(r.x), "=f"(r.y) : "l"(v)); return r;
}
#define FMA2(acc, a, b) asm("fma.rn.f32x2 %0, %1, %2, %0;" : "+l"(acc) : "l"(a), "l"(b))

// ---------------------------------------------------------------------------
// K1: qkv = x @ Wqkv^T -> scatter-transposed into g_qkvT
// 128x128 tile, BK=16, 256 threads, 8x8 microtile (f32x2-packed along cols)
// ---------------------------------------------------------------------------
__global__ __launch_bounds__(256, 2)
void k_qkv_gemm(const float* __restrict__ x, const float* __restrict__ w)
{
    __shared__ float As[16][132];
    __shared__ float Bs[16][132];
    const int tid = threadIdx.x;
    const int tx = tid & 15, ty = tid >> 4;
    const int row0 = blockIdx.y * 128;
    const int col0 = blockIdx.x * 128;

    u64 acc[8][4];
#pragma unroll
    for (int i = 0; i < 8; i++)
#pragma unroll
        for (int j = 0; j < 4; j++) acc[i][j] = 0ULL;

    const int lr = tid >> 1;          // 0..127
    const int lk = (tid & 1) * 8;     // 0 or 8
    const float* xa = x + (size_t)(row0 + lr) * C_ + lk;
    const float* wb = w + (size_t)(col0 + lr) * C_ + lk;

    for (int k0 = 0; k0 < C_; k0 += 16) {
        float4 a0 = *(const float4*)(xa + k0);
        float4 a1 = *(const float4*)(xa + k0 + 4);
        float4 b0 = *(const float4*)(wb + k0);
        float4 b1 = *(const float4*)(wb + k0 + 4);
        As[lk + 0][lr] = a0.x; As[lk + 1][lr] = a0.y; As[lk + 2][lr] = a0.z; As[lk + 3][lr] = a0.w;
        As[lk + 4][lr] = a1.x; As[lk + 5][lr] = a1.y; As[lk + 6][lr] = a1.z; As[lk + 7][lr] = a1.w;
        Bs[lk + 0][lr] = b0.x; Bs[lk + 1][lr] = b0.y; Bs[lk + 2][lr] = b0.z; Bs[lk + 3][lr] = b0.w;
        Bs[lk + 4][lr] = b1.x; Bs[lk + 5][lr] = b1.y; Bs[lk + 6][lr] = b1.z; Bs[lk + 7][lr] = b1.w;
        __syncthreads();
#pragma unroll
        for (int kk = 0; kk < 16; kk++) {
            float4 av0 = *(const float4*)&As[kk][ty * 8];
            float4 av1 = *(const float4*)&As[kk][ty * 8 + 4];
            ulonglong2 bv0 = *(const ulonglong2*)&Bs[kk][tx * 8];
            ulonglong2 bv1 = *(const ulonglong2*)&Bs[kk][tx * 8 + 4];
            u64 bp[4] = {bv0.x, bv0.y, bv1.x, bv1.y};
            float a[8] = {av0.x, av0.y, av0.z, av0.w, av1.x, av1.y, av1.z, av1.w};
#pragma unroll
            for (int i = 0; i < 8; i++) {
                u64 ap = pk2(a[i], a[i]);
#pragma unroll
                for (int j = 0; j < 4; j++) FMA2(acc[i][j], ap, bp[j]);
            }
        }
        __syncthreads();
    }

    // Epilogue: col c -> which=c/384, cc=c%384; qkvT row = which*3072 + b*384 + cc
    const int b = row0 >> 13;                 // 128 | 8192, tile never crosses b
    const int nbase = (row0 & (N_ - 1)) + ty * 8;
#pragma unroll
    for (int j2 = 0; j2 < 4; j2++) {
        float2 col01[8];
#pragma unroll
        for (int i = 0; i < 8; i++) col01[i] = upk(acc[i][j2]);
#pragma unroll
        for (int s = 0; s < 2; s++) {
            int c = col0 + tx * 8 + j2 * 2 + s;
            int which = c / C_;
            int cc = c - which * C_;
            size_t off = ((size_t)(which * 3072 + b * C_ + cc)) * N_ + nbase;
            float4 v0, v1;
            if (s == 0) {
                v0 = make_float4(col01[0].x, col01[1].x, col01[2].x, col01[3].x);
                v1 = make_float4(col01[4].x, col01[5].x, col01[6].x, col01[7].x);
            } else {
                v0 = make_float4(col01[0].y, col01[1].y, col01[2].y, col01[3].y);
                v1 = make_float4(col01[4].y, col01[5].y, col01[6].y, col01[7].y);
            }
            *(float4*)(g_qkvT + off) = v0;
            *(float4*)(g_qkvT + off + 4) = v1;
        }
    }
}

// ---------------------------------------------------------------------------
// K2a: reciprocal L2 norms of q and k rows (6144 rows of 8192)
// ---------------------------------------------------------------------------
__global__ void k_norms()
{
    const int idx = blockIdx.x;
    const float4* row = (const float4*)(g_qkvT + (size_t)idx * N_);
    float s = 0.f;
    for (int i = threadIdx.x; i < N_ / 4; i += 256) {
        float4 v = row[i];
        s += v.x * v.x + v.y * v.y + v.z * v.z + v.w * v.w;
    }
    __shared__ float red[256];
    red[threadIdx.x] = s;
    __syncthreads();
    for (int off = 128; off > 0; off >>= 1) {
        if (threadIdx.x < off) red[threadIdx.x] += red[threadIdx.x + off];
        __syncthreads();
    }
    if (threadIdx.x == 0)
        g_rn[idx] = 1.0f / fmaxf(sqrtf(red[0]), 1e-12f);
}

// ---------------------------------------------------------------------------
// K2b: raw Gram partials  Spart[chunk][bh][d][e] = sum_{n in chunk} q[d,n]k[e,n]
// ---------------------------------------------------------------------------
__global__ void k_logits()
{
    const int chunk = blockIdx.x;     // 0..7 (1024 n each)
    const int bh    = blockIdx.y;     // 0..63
    const int tid   = threadIdx.x;
    __shared__ float Qs[32][49];
    __shared__ float Ks[32][49];

    const int td = (tid >> 4) * 3;
    const int te = (tid & 15) * 3;
    float acc[3][3] = {};

    const size_t qbase = (size_t)(bh * 48) * N_ + (size_t)chunk * 1024;
    const size_t kbase = qbase + (size_t)3072 * N_;

    for (int t = 0; t < 1024; t += 32) {
#pragma unroll
        for (int it = 0; it < 3; it++) {
            int id  = tid + it * 256;
            int isK = (id >= 384);
            int lid = id - isK * 384;
            int d = lid >> 3;
            int nseg = (lid & 7) * 4;
            size_t base = isK ? kbase : qbase;
            float4 v = *(const float4*)(g_qkvT + base + (size_t)d * N_ + t + nseg);
            float (*S)[49] = isK ? Ks : Qs;
            S[nseg + 0][d] = v.x; S[nseg + 1][d] = v.y;
            S[nseg + 2][d] = v.z; S[nseg + 3][d] = v.w;
        }
        __syncthreads();
#pragma unroll
        for (int kk = 0; kk < 32; kk++) {
            float q0 = Qs[kk][td], q1 = Qs[kk][td + 1], q2 = Qs[kk][td + 2];
            float p0 = Ks[kk][te], p1 = Ks[kk][te + 1], p2 = Ks[kk][te + 2];
            acc[0][0] += q0 * p0; acc[0][1] += q0 * p1; acc[0][2] += q0 * p2;
            acc[1][0] += q1 * p0; acc[1][1] += q1 * p1; acc[1][2] += q1 * p2;
            acc[2][0] += q2 * p0; acc[2][1] += q2 * p1; acc[2][2] += q2 * p2;
        }
        __syncthreads();
    }

    float* outp = g_Spart + ((size_t)chunk * 64 + bh) * 2304;
#pragma unroll
    for (int i = 0; i < 3; i++)
#pragma unroll
        for (int j = 0; j < 3; j++)
            outp[(td + i) * 48 + (te + j)] = acc[i][j];
}

// ---------------------------------------------------------------------------
// K2c: sum partials, norm-scale, softmax over e, write transposed attn
// ---------------------------------------------------------------------------
__global__ void k_softmax()
{
    const int bh = blockIdx.x;
    const int d  = threadIdx.x;
    if (d >= 48) return;
    const float rq = g_rn[bh * 48 + d];
    const float* rk = g_rn + 3072 + bh * 48;

    float vals[48];
    float mx = -1e30f;
#pragma unroll
    for (int e = 0; e < 48; e++) {
        float s = 0.f;
#pragma unroll
        for (int c = 0; c < 8; c++)
            s += g_Spart[((size_t)c * 64 + bh) * 2304 + d * 48 + e];
        float v = s * rq * rk[e];
        vals[e] = v;
        mx = fmaxf(mx, v);
    }
    float sum = 0.f;
#pragma unroll
    for (int e = 0; e < 48; e++) {
        vals[e] = expf(vals[e] - mx);
        sum += vals[e];
    }
    float inv = 1.0f / sum;
#pragma unroll
    for (int e = 0; e < 48; e++)
        g_attnT[(size_t)bh * 2304 + e * 48 + d] = vals[e] * inv;
}

// ---------------------------------------------------------------------------
// K2d: y[b,h,d,n] = sum_e attn[d,e] * v[e,n]   (f32x2-packed along d)
// ---------------------------------------------------------------------------
__global__ void k_av()
{
    const int chunk = blockIdx.x;     // 0..31 (256 n each)
    const int bh    = blockIdx.y;
    const int tid   = threadIdx.x;
    __shared__ __align__(16) float At[2304];   // At[e*48 + d]
#pragma unroll
    for (int i = 0; i < 9; i++)
        At[tid + i * 256] = g_attnT[(size_t)bh * 2304 + tid + i * 256];
    __syncthreads();

    const int n = chunk * 256 + tid;
    const size_t vbase = ((size_t)(2 * 3072 + bh * 48)) * N_ + n;
    u64 acc2[24];
#pragma unroll
    for (int i = 0; i < 24; i++) acc2[i] = 0ULL;

#pragma unroll 4
    for (int e = 0; e < 48; e++) {
        float vv = g_qkvT[vbase + (size_t)e * N_];
        u64 vp = pk2(vv, vv);
        const ulonglong2* arow = (const ulonglong2*)&At[e * 48];
#pragma unroll
        for (int t = 0; t < 12; t++) {
            ulonglong2 a2 = arow[t];
            FMA2(acc2[2 * t + 0], a2.x, vp);
            FMA2(acc2[2 * t + 1], a2.y, vp);
        }
    }
    const size_t ybase = (size_t)(bh * 48) * N_ + n;
#pragma unroll
    for (int t = 0; t < 24; t++) {
        float2 f = upk(acc2[t]);
        g_y[ybase + (size_t)(2 * t + 0) * N_] = f.x;
        g_y[ybase + (size_t)(2 * t + 1) * N_] = f.y;
    }
}

// ---------------------------------------------------------------------------
// K3: out[b,n,c] = sum_j y[b*384+j, n] * w_proj[c][j] + b_proj[c]
// 128x128 tile (f32x2-packed along c); A gathered n-contiguous from g_y
// ---------------------------------------------------------------------------
__global__ __launch_bounds__(256, 2)
void k_proj_gemm(const float* __restrict__ wp,
                 const float* __restrict__ bp,
                 float* __restrict__ out)
{
    __shared__ float As[16][132];   // As[j_local][m_local]
    __shared__ float Bs[16][132];   // Bs[k_local][c_local]
    const int tid = threadIdx.x;
    const int tx = tid & 15, ty = tid >> 4;
    const int row0 = blockIdx.y * 128;
    const int col0 = blockIdx.x * 128;
    const int b  = row0 >> 13;
    const int n0 = row0 & (N_ - 1);

    u64 acc[8][4];
#pragma unroll
    for (int i = 0; i < 8; i++)
#pragma unroll
        for (int j = 0; j < 4; j++) acc[i][j] = 0ULL;

    const int jl  = tid >> 4;          // 0..15
    const int seg = (tid & 15) * 8;    // 0..120
    const int lr  = tid >> 1;          // 0..127
    const int lk  = (tid & 1) * 8;
    const float* wrow = wp + (size_t)(col0 + lr) * C_ + lk;

    for (int k0 = 0; k0 < C_; k0 += 16) {
        const float* ya = g_y + ((size_t)(b * C_ + k0 + jl)) * N_ + n0 + seg;
        float4 a0 = *(const float4*)(ya);
        float4 a1 = *(const float4*)(ya + 4);
        *(float4*)&As[jl][seg] = a0;
        *(float4*)&As[jl][seg + 4] = a1;
        float4 b0 = *(const float4*)(wrow + k0);
        float4 b1 = *(const float4*)(wrow + k0 + 4);
        Bs[lk + 0][lr] = b0.x; Bs[lk + 1][lr] = b0.y; Bs[lk + 2][lr] = b0.z; Bs[lk + 3][lr] = b0.w;
        Bs[lk + 4][lr] = b1.x; Bs[lk + 5][lr] = b1.y; Bs[lk + 6][lr] = b1.z; Bs[lk + 7][lr] = b1.w;
        __syncthreads();
#pragma unroll
        for (int kk = 0; kk < 16; kk++) {
            float4 av0 = *(const float4*)&As[kk][ty * 8];
            float4 av1 = *(const float4*)&As[kk][ty * 8 + 4];
            ulonglong2 bv0 = *(const ulonglong2*)&Bs[kk][tx * 8];
            ulonglong2 bv1 = *(const ulonglong2*)&Bs[kk][tx * 8 + 4];
            u64 bp4[4] = {bv0.x, bv0.y, bv1.x, bv1.y};
            float a[8] = {av0.x, av0.y, av0.z, av0.w, av1.x, av1.y, av1.z, av1.w};
#pragma unroll
            for (int i = 0; i < 8; i++) {
                u64 ap = pk2(a[i], a[i]);
#pragma unroll
                for (int j = 0; j < 4; j++) FMA2(acc[i][j], ap, bp4[j]);
            }
        }
        __syncthreads();
    }

    // Epilogue: out row-major [m][c]; packed pairs are along c -> contiguous
    const int c0 = col0 + tx * 8;
    float4 bias0 = *(const float4*)(bp + c0);
    float4 bias1 = *(const float4*)(bp + c0 + 4);
#pragma unroll
    for (int i = 0; i < 8; i++) {
        int m = row0 + ty * 8 + i;
        float2 p0 = upk(acc[i][0]);
        float2 p1 = upk(acc[i][1]);
        float2 p2 = upk(acc[i][2]);
        float2 p3 = upk(acc[i][3]);
        float4 v0 = make_float4(p0.x + bias0.x, p0.y + bias0.y, p1.x + bias0.z, p1.y + bias0.w);
        float4 v1 = make_float4(p2.x + bias1.x, p2.y + bias1.y, p3.x + bias1.z, p3.y + bias1.w);
        *(float4*)(out + (size_t)m * C_ + c0) = v0;
        *(float4*)(out + (size_t)m * C_ + c0 + 4) = v1;
    }
}

// ---------------------------------------------------------------------------
extern "C" void kernel_launch(void* const* d_in, const int* in_sizes, int n_in,
                              void* d_out, int out_size)
{
    const float* x      = (const float*)d_in[0];
    const float* w_qkv  = (const float*)d_in[1];
    const float* w_proj = (const float*)d_in[2];
    const float* b_proj = (const float*)d_in[3];
    float* out = (float*)d_out;

    dim3 g1(QKVC / 128, M_ / 128);        // 9 x 512
    k_qkv_gemm<<<g1, 256>>>(x, w_qkv);

    k_norms<<<6144, 256>>>();

    dim3 g2(8, 64);
    k_logits<<<g2, 256>>>();

    k_softmax<<<64, 48>>>();

    dim3 g3(32, 64);
    k_av<<<g3, 256>>>();

    dim3 g4(C_ / 128, M_ / 128);          // 3 x 512
    k_proj_gemm<<<g4, 256>>>(w_proj, b_proj, out);
}

// round 4
// speedup vs baseline: 1.9740x; 1.6202x over previous
#include <cuda_runtime.h>
#include <cuda_bf16.h>
#include <math.h>
#include <stdint.h>

#define B_   8
#define N_   8192
#define C_   384
#define M_   65536
#define QKVC 1152

typedef unsigned long long u64;
typedef unsigned int u32;

// Scratch (static device arrays)
__device__ float g_qkvT[9216L * N_];          // [which(3)][b][h][d][n]
__device__ float g_rn[6144];
__device__ float g_Spart[8 * 64 * 2304];
__device__ float g_attnT[64 * 2304];
__device__ __nv_bfloat16 g_xhi[(size_t)M_ * C_], g_xlo[(size_t)M_ * C_];
__device__ __nv_bfloat16 g_yhi[(size_t)M_ * C_], g_ylo[(size_t)M_ * C_];
__device__ __nv_bfloat16 g_wqhi[QKVC * C_], g_wqlo[QKVC * C_];
__device__ __nv_bfloat16 g_wphi[C_ * C_], g_wplo[C_ * C_];

// ---- helpers ----------------------------------------------------------------
__device__ __forceinline__ u64 pk2(float a, float b) {
    u64 r; asm("mov.b64 %0, {%1,%2};" : "=l"(r) : "f"(a), "f"(b)); return r;
}
__device__ __forceinline__ float2 upk(u64 v) {
    float2 r; asm("mov.b64 {%0,%1}, %2;" : "=f"(r.x), "=f"(r.y) : "l"(v)); return r;
}
#define FMA2(acc, a, b) asm("fma.rn.f32x2 %0, %1, %2, %0;" : "+l"(acc) : "l"(a), "l"(b))

__device__ __forceinline__ u32 s2u(const void* p) {
    u32 a;
    asm("{ .reg .u64 t; cvta.to.shared.u64 t, %1; cvt.u32.u64 %0, t; }" : "=r"(a) : "l"(p));
    return a;
}
__device__ __forceinline__ void cp16(u32 dst, const void* src) {
    asm volatile("cp.async.cg.shared.global [%0], [%1], 16;" :: "r"(dst), "l"(src));
}
__device__ __forceinline__ void ldsm4(u32* r, u32 addr) {
    asm volatile("ldmatrix.sync.aligned.m8n8.x4.shared.b16 {%0,%1,%2,%3}, [%4];"
        : "=r"(r[0]), "=r"(r[1]), "=r"(r[2]), "=r"(r[3]) : "r"(addr));
}
__device__ __forceinline__ void mma_bf16(float* d, const u32* a, u32 b0, u32 b1) {
    asm volatile("mma.sync.aligned.m16n8k16.row.col.f32.bf16.bf16.f32 "
        "{%0,%1,%2,%3}, {%4,%5,%6,%7}, {%8,%9}, {%0,%1,%2,%3};"
        : "+f"(d[0]), "+f"(d[1]), "+f"(d[2]), "+f"(d[3])
        : "r"(a[0]), "r"(a[1]), "r"(a[2]), "r"(a[3]), "r"(b0), "r"(b1));
}
__device__ __forceinline__ void split2(float a, float b, u32& hi, u32& lo) {
    __nv_bfloat16 ha = __float2bfloat16(a), hb = __float2bfloat16(b);
    __nv_bfloat16 la = __float2bfloat16(a - __bfloat162float(ha));
    __nv_bfloat16 lb = __float2bfloat16(b - __bfloat162float(hb));
    hi = (u32)*(unsigned short*)&ha | ((u32)*(unsigned short*)&hb << 16);
    lo = (u32)*(unsigned short*)&la | ((u32)*(unsigned short*)&lb << 16);
}

// ---------------------------------------------------------------------------
// Pre-split fp32 -> bf16 hi/lo   (SEL: 0=x, 1=w_qkv, 2=w_proj)
// ---------------------------------------------------------------------------
template<int SEL>
__global__ void k_split(const float* __restrict__ src, int n4)
{
    __nv_bfloat16* hi = (SEL == 0) ? g_xhi : (SEL == 1) ? g_wqhi : g_wphi;
    __nv_bfloat16* lo = (SEL == 0) ? g_xlo : (SEL == 1) ? g_wqlo : g_wplo;
    int i = blockIdx.x * 256 + threadIdx.x;
    if (i >= n4) return;
    float4 v = ((const float4*)src)[i];
    u32 h0, l0, h1, l1;
    split2(v.x, v.y, h0, l0);
    split2(v.z, v.w, h1, l1);
    ((uint2*)hi)[i] = make_uint2(h0, h1);
    ((uint2*)lo)[i] = make_uint2(l0, l1);
}

// ---------------------------------------------------------------------------
// Tensor-core GEMM (mma.sync bf16, hi/lo split), C = A(m,k) * B(n,k)^T, K=384
// MODE 0: A = x(hi/lo), B = w_qkv -> scatter-transpose into g_qkvT
// MODE 1: A = y(hi/lo), B = w_proj -> +bias, row-major out
// CTA tile 128x128, BK=16, 24 k-iters, double-buffered cp.async
// ---------------------------------------------------------------------------
#define GEMM_SMEM 34816   // max(2 stages * 16KB, T stage 128*68*4)

template<int MODE>
__global__ void __launch_bounds__(256, 1)
k_gemm(const float* __restrict__ bias, float* __restrict__ outp)
{
    extern __shared__ char smem[];
    const u32 sb = s2u(smem);
    const int tid  = threadIdx.x;
    const int lane = tid & 31, wid = tid >> 5;
    const int wm = wid & 1, wn = wid >> 1;          // warp grid 2m x 4n
    const int row0 = blockIdx.y * 128;
    const int col0 = blockIdx.x * 128;

    const __nv_bfloat16* Ahi = (MODE == 0) ? g_xhi  : g_yhi;
    const __nv_bfloat16* Alo = (MODE == 0) ? g_xlo  : g_ylo;
    const __nv_bfloat16* Bhi = (MODE == 0) ? g_wqhi : g_wphi;
    const __nv_bfloat16* Blo = (MODE == 0) ? g_wqlo : g_wplo;

    float acc[4][4][4];
#pragma unroll
    for (int a = 0; a < 4; a++)
#pragma unroll
        for (int b = 0; b < 4; b++)
#pragma unroll
            for (int c = 0; c < 4; c++) acc[a][b][c] = 0.f;

    // cp.async: tile = 128 rows x 16 bf16 (32B row = 2 chunks of 16B), 256 chunks
    const int crow = tid >> 1;
    const int cch  = tid & 1;
    const int cphys = cch ^ ((crow >> 2) & 1);
    const u32 cso = crow * 32 + cphys * 16;
    const size_t gra = (size_t)(row0 + crow) * C_ + cch * 8;
    const size_t grb = (size_t)(col0 + crow) * C_ + cch * 8;

    auto load_tile = [&](int it, int s) {
        const u32 st = sb + s * 16384;
        const int k0 = it * 16;
        cp16(st +     0 + cso, Ahi + gra + k0);
        cp16(st +  4096 + cso, Alo + gra + k0);
        cp16(st +  8192 + cso, Bhi + grb + k0);
        cp16(st + 12288 + cso, Blo + grb + k0);
    };

    // ldmatrix.x4 address for 16-row group starting at r (row stride 32B)
    const int fr_off = (lane & 7) + ((lane >> 3) & 1) * 8;
    const int fr_ch  = lane >> 4;
    auto frag_addr = [&](u32 base, int r) -> u32 {
        int row = r + fr_off;
        int phys = fr_ch ^ ((row >> 2) & 1);
        return base + row * 32 + phys * 16;
    };

    auto compute = [&](int s) {
        const u32 st = sb + s * 16384;
        u32 ah[4][4], al[4][4], bh[2][4], bl[2][4];
#pragma unroll
        for (int mt = 0; mt < 4; mt++) {
            ldsm4(ah[mt], frag_addr(st +    0, wm * 64 + mt * 16));
            ldsm4(al[mt], frag_addr(st + 4096, wm * 64 + mt * 16));
        }
#pragma unroll
        for (int np = 0; np < 2; np++) {
            ldsm4(bh[np], frag_addr(st +  8192, wn * 32 + np * 16));
            ldsm4(bl[np], frag_addr(st + 12288, wn * 32 + np * 16));
        }
#pragma unroll
        for (int mt = 0; mt < 4; mt++)
#pragma unroll
            for (int np = 0; np < 2; np++)
#pragma unroll
                for (int sub = 0; sub < 2; sub++) {
                    int nt = np * 2 + sub;
                    mma_bf16(acc[mt][nt], ah[mt], bh[np][sub], bh[np][sub + 2]);
                    mma_bf16(acc[mt][nt], ah[mt], bl[np][sub], bl[np][sub + 2]);
                    mma_bf16(acc[mt][nt], al[mt], bh[np][sub], bh[np][sub + 2]);
                }
    };

    load_tile(0, 0);
    asm volatile("cp.async.commit_group;" ::: "memory");
#pragma unroll 1
    for (int it = 0; it < 24; it++) {
        if (it) __syncthreads();
        if (it + 1 < 24) {
            load_tile(it + 1, (it + 1) & 1);
            asm volatile("cp.async.commit_group;" ::: "memory");
            asm volatile("cp.async.wait_group 1;" ::: "memory");
        } else {
            asm volatile("cp.async.wait_group 0;" ::: "memory");
        }
        __syncthreads();
        compute(it & 1);
    }

    // Epilogue: stage halves through smem T[128][68] for coalesced stores
    float* T = (float*)smem;
    const int g = lane >> 2, tq = lane & 3;
#pragma unroll 1
    for (int jh = 0; jh < 2; jh++) {
        __syncthreads();
        if (MODE == 0) {
            if (wm == jh) {
#pragma unroll
                for (int mt = 0; mt < 4; mt++)
#pragma unroll
                    for (int nt = 0; nt < 4; nt++) {
                        int ml = mt * 16 + g;
                        int nl = wn * 32 + nt * 8 + tq * 2;
#pragma unroll
                        for (int rr = 0; rr < 4; rr++)
                            T[(nl + (rr & 1)) * 68 + ml + (rr >> 1) * 8] = acc[mt][nt][rr];
                    }
            }
        } else {
            if ((wn >> 1) == jh) {
#pragma unroll
                for (int mt = 0; mt < 4; mt++)
#pragma unroll
                    for (int nt = 0; nt < 4; nt++) {
                        int ml = wm * 64 + mt * 16 + g;
                        int nl = (wn & 1) * 32 + nt * 8 + tq * 2;
#pragma unroll
                        for (int rr = 0; rr < 4; rr++)
                            T[(ml + (rr >> 1) * 8) * 68 + nl + (rr & 1)] = acc[mt][nt][rr];
                    }
            }
        }
        __syncthreads();
        if (MODE == 0) {
            const int bb = row0 >> 13;
            const int n0 = (row0 & (N_ - 1)) + jh * 64;
            const int which = col0 / C_;          // 128-tiles never cross 384 bnd
            const int ccb = col0 - which * C_;
#pragma unroll
            for (int t = 0; t < 8; t++) {
                int fid = tid + t * 256;
                int i = fid >> 4;                  // 0..127 (output channel cc)
                int j = (fid & 15) * 4;            // 0..60 (n offset)
                float4 v = *(float4*)&T[i * 68 + j];
                *(float4*)(g_qkvT + ((size_t)(which * 3072 + bb * C_ + ccb + i)) * N_ + n0 + j) = v;
            }
        } else {
            const int c0 = col0 + jh * 64;
#pragma unroll
            for (int t = 0; t < 8; t++) {
                int fid = tid + t * 256;
                int i = fid >> 4;                  // 0..127 (m)
                int j = (fid & 15) * 4;
                float4 v = *(float4*)&T[i * 68 + j];
                float4 bv = *(const float4*)(bias + c0 + j);
                v.x += bv.x; v.y += bv.y; v.z += bv.z; v.w += bv.w;
                *(float4*)(outp + (size_t)(row0 + i) * C_ + c0 + j) = v;
            }
        }
    }
}

// ---------------------------------------------------------------------------
// K2a: reciprocal L2 norms of q and k rows
// ---------------------------------------------------------------------------
__global__ void k_norms()
{
    const int idx = blockIdx.x;
    const float4* row = (const float4*)(g_qkvT + (size_t)idx * N_);
    float s = 0.f;
    for (int i = threadIdx.x; i < N_ / 4; i += 256) {
        float4 v = row[i];
        s += v.x * v.x + v.y * v.y + v.z * v.z + v.w * v.w;
    }
    __shared__ float red[256];
    red[threadIdx.x] = s;
    __syncthreads();
    for (int off = 128; off > 0; off >>= 1) {
        if (threadIdx.x < off) red[threadIdx.x] += red[threadIdx.x + off];
        __syncthreads();
    }
    if (threadIdx.x == 0)
        g_rn[idx] = 1.0f / fmaxf(sqrtf(red[0]), 1e-12f);
}

// ---------------------------------------------------------------------------
// K2b: Gram partials
// ---------------------------------------------------------------------------
__global__ void k_logits()
{
    const int chunk = blockIdx.x;
    const int bh    = blockIdx.y;
    const int tid   = threadIdx.x;
    __shared__ float Qs[32][49];
    __shared__ float Ks[32][49];

    const int td = (tid >> 4) * 3;
    const int te = (tid & 15) * 3;
    float acc[3][3] = {};

    const size_t qbase = (size_t)(bh * 48) * N_ + (size_t)chunk * 1024;
    const size_t kbase = qbase + (size_t)3072 * N_;

    for (int t = 0; t < 1024; t += 32) {
#pragma unroll
        for (int it = 0; it < 3; it++) {
            int id  = tid + it * 256;
            int isK = (id >= 384);
            int lidx = id - isK * 384;
            int d = lidx >> 3;
            int nseg = (lidx & 7) * 4;
            size_t base = isK ? kbase : qbase;
            float4 v = *(const float4*)(g_qkvT + base + (size_t)d * N_ + t + nseg);
            float (*S)[49] = isK ? Ks : Qs;
            S[nseg + 0][d] = v.x; S[nseg + 1][d] = v.y;
            S[nseg + 2][d] = v.z; S[nseg + 3][d] = v.w;
        }
        __syncthreads();
#pragma unroll
        for (int kk = 0; kk < 32; kk++) {
            float q0 = Qs[kk][td], q1 = Qs[kk][td + 1], q2 = Qs[kk][td + 2];
            float p0 = Ks[kk][te], p1 = Ks[kk][te + 1], p2 = Ks[kk][te + 2];
            acc[0][0] += q0 * p0; acc[0][1] += q0 * p1; acc[0][2] += q0 * p2;
            acc[1][0] += q1 * p0; acc[1][1] += q1 * p1; acc[1][2] += q1 * p2;
            acc[2][0] += q2 * p0; acc[2][1] += q2 * p1; acc[2][2] += q2 * p2;
        }
        __syncthreads();
    }

    float* outp = g_Spart + ((size_t)chunk * 64 + bh) * 2304;
#pragma unroll
    for (int i = 0; i < 3; i++)
#pragma unroll
        for (int j = 0; j < 3; j++)
            outp[(td + i) * 48 + (te + j)] = acc[i][j];
}

// ---------------------------------------------------------------------------
// K2c: softmax
// ---------------------------------------------------------------------------
__global__ void k_softmax()
{
    const int bh = blockIdx.x;
    const int d  = threadIdx.x;
    if (d >= 48) return;
    const float rq = g_rn[bh * 48 + d];
    const float* rk = g_rn + 3072 + bh * 48;

    float vals[48];
    float mx = -1e30f;
#pragma unroll
    for (int e = 0; e < 48; e++) {
        float s = 0.f;
#pragma unroll
        for (int c = 0; c < 8; c++)
            s += g_Spart[((size_t)c * 64 + bh) * 2304 + d * 48 + e];
        float v = s * rq * rk[e];
        vals[e] = v;
        mx = fmaxf(mx, v);
    }
    float sum = 0.f;
#pragma unroll
    for (int e = 0; e < 48; e++) {
        vals[e] = expf(vals[e] - mx);
        sum += vals[e];
    }
    float inv = 1.0f / sum;
#pragma unroll
    for (int e = 0; e < 48; e++)
        g_attnT[(size_t)bh * 2304 + e * 48 + d] = vals[e] * inv;
}

// ---------------------------------------------------------------------------
// K2d: y = attn @ v, emitted as bf16 hi/lo, row-major [m][j] for K3
// ---------------------------------------------------------------------------
__global__ void k_av()
{
    const int chunk = blockIdx.x;     // 0..31 (256 n each)
    const int bh    = blockIdx.y;
    const int tid   = threadIdx.x;
    __shared__ __align__(16) float At[2304];   // At[e*48 + d]
#pragma unroll
    for (int i = 0; i < 9; i++)
        At[tid + i * 256] = g_attnT[(size_t)bh * 2304 + tid + i * 256];
    __syncthreads();

    const int n = chunk * 256 + tid;
    const size_t vbase = ((size_t)(2 * 3072 + bh * 48)) * N_ + n;
    u64 acc2[24];
#pragma unroll
    for (int i = 0; i < 24; i++) acc2[i] = 0ULL;

#pragma unroll 4
    for (int e = 0; e < 48; e++) {
        float vv = g_qkvT[vbase + (size_t)e * N_];
        u64 vp = pk2(vv, vv);
        const ulonglong2* arow = (const ulonglong2*)&At[e * 48];
#pragma unroll
        for (int t = 0; t < 12; t++) {
            ulonglong2 a2 = arow[t];
            FMA2(acc2[2 * t + 0], a2.x, vp);
            FMA2(acc2[2 * t + 1], a2.y, vp);
        }
    }
    const int b = bh >> 3, h = bh & 7;
    const size_t base = ((size_t)(b * N_ + n)) * C_ + h * 48;   // even -> u32 aligned
    u32* yh = (u32*)(g_yhi + base);
    u32* yl = (u32*)(g_ylo + base);
#pragma unroll
    for (int t = 0; t < 12; t++) {
        float2 f0 = upk(acc2[2 * t + 0]);
        float2 f1 = upk(acc2[2 * t + 1]);
        u32 h0, l0, h1, l1;
        split2(f0.x, f0.y, h0, l0);
        split2(f1.x, f1.y, h1, l1);
        yh[2 * t + 0] = h0; yh[2 * t + 1] = h1;
        yl[2 * t + 0] = l0; yl[2 * t + 1] = l1;
    }
}

// ---------------------------------------------------------------------------
extern "C" void kernel_launch(void* const* d_in, const int* in_sizes, int n_in,
                              void* d_out, int out_size)
{
    const float* x      = (const float*)d_in[0];
    const float* w_qkv  = (const float*)d_in[1];
    const float* w_proj = (const float*)d_in[2];
    const float* b_proj = (const float*)d_in[3];
    float* out = (float*)d_out;

    const int n4x = M_ * C_ / 4;          // 6291456
    const int n4q = QKVC * C_ / 4;        // 110592
    const int n4p = C_ * C_ / 4;          // 36864
    k_split<0><<<(n4x + 255) / 256, 256>>>(x, n4x);
    k_split<1><<<(n4q + 255) / 256, 256>>>(w_qkv, n4q);
    k_split<2><<<(n4p + 255) / 256, 256>>>(w_proj, n4p);

    dim3 g1(QKVC / 128, M_ / 128);        // 9 x 512
    k_gemm<0><<<g1, 256, GEMM_SMEM>>>(nullptr, nullptr);

    k_norms<<<6144, 256>>>();

    dim3 g2(8, 64);
    k_logits<<<g2, 256>>>();

    k_softmax<<<64, 48>>>();

    dim3 g3(32, 64);
    k_av<<<g3, 256>>>();

    dim3 g4(C_ / 128, M_ / 128);          // 3 x 512
    k_gemm<1><<<g4, 256, GEMM_SMEM>>>(b_proj, out);
}

// round 5
// speedup vs baseline: 1.9817x; 1.0039x over previous
#include <cuda_runtime.h>
#include <cuda_bf16.h>
#include <math.h>
#include <stdint.h>

#define B_   8
#define N_   8192
#define C_   384
#define M_   65536
#define QKVC 1152

typedef unsigned long long u64;
typedef unsigned int u32;

// Scratch (static device arrays)
__device__ float g_qkvT[9216L * N_];          // [which(3)][b][h][d][n]
__device__ float g_rn[6144];
__device__ float g_Spart[8 * 64 * 2304];
__device__ float g_attnT[64 * 2304];
__device__ __nv_bfloat16 g_xhi[(size_t)M_ * C_], g_xlo[(size_t)M_ * C_];
__device__ __nv_bfloat16 g_yhi[(size_t)M_ * C_], g_ylo[(size_t)M_ * C_];
__device__ __nv_bfloat16 g_wqhi[QKVC * C_], g_wqlo[QKVC * C_];
__device__ __nv_bfloat16 g_wphi[C_ * C_], g_wplo[C_ * C_];

// ---- helpers ----------------------------------------------------------------
__device__ __forceinline__ u64 pk2(float a, float b) {
    u64 r; asm("mov.b64 %0, {%1,%2};" : "=l"(r) : "f"(a), "f"(b)); return r;
}
__device__ __forceinline__ float2 upk(u64 v) {
    float2 r; asm("mov.b64 {%0,%1}, %2;" : "=f"(r.x), "=f"(r.y) : "l"(v)); return r;
}
#define FMA2(acc, a, b) asm("fma.rn.f32x2 %0, %1, %2, %0;" : "+l"(acc) : "l"(a), "l"(b))

__device__ __forceinline__ u32 s2u(const void* p) {
    u32 a;
    asm("{ .reg .u64 t; cvta.to.shared.u64 t, %1; cvt.u32.u64 %0, t; }" : "=r"(a) : "l"(p));
    return a;
}
__device__ __forceinline__ void cp16(u32 dst, const void* src) {
    asm volatile("cp.async.cg.shared.global [%0], [%1], 16;" :: "r"(dst), "l"(src));
}
__device__ __forceinline__ void ldsm4(u32* r, u32 addr) {
    asm volatile("ldmatrix.sync.aligned.m8n8.x4.shared.b16 {%0,%1,%2,%3}, [%4];"
        : "=r"(r[0]), "=r"(r[1]), "=r"(r[2]), "=r"(r[3]) : "r"(addr));
}
__device__ __forceinline__ void mma_bf16(float* d, const u32* a, u32 b0, u32 b1) {
    asm volatile("mma.sync.aligned.m16n8k16.row.col.f32.bf16.bf16.f32 "
        "{%0,%1,%2,%3}, {%4,%5,%6,%7}, {%8,%9}, {%0,%1,%2,%3};"
        : "+f"(d[0]), "+f"(d[1]), "+f"(d[2]), "+f"(d[3])
        : "r"(a[0]), "r"(a[1]), "r"(a[2]), "r"(a[3]), "r"(b0), "r"(b1));
}
__device__ __forceinline__ void split2(float a, float b, u32& hi, u32& lo) {
    __nv_bfloat16 ha = __float2bfloat16(a), hb = __float2bfloat16(b);
    __nv_bfloat16 la = __float2bfloat16(a - __bfloat162float(ha));
    __nv_bfloat16 lb = __float2bfloat16(b - __bfloat162float(hb));
    hi = (u32)*(unsigned short*)&ha | ((u32)*(unsigned short*)&hb << 16);
    lo = (u32)*(unsigned short*)&la | ((u32)*(unsigned short*)&lb << 16);
}

// ---------------------------------------------------------------------------
// Pre-split fp32 -> bf16 hi/lo   (SEL: 0=x, 1=w_qkv, 2=w_proj)
// ---------------------------------------------------------------------------
template<int SEL>
__global__ void k_split(const float* __restrict__ src, int n4)
{
    __nv_bfloat16* hi = (SEL == 0) ? g_xhi : (SEL == 1) ? g_wqhi : g_wphi;
    __nv_bfloat16* lo = (SEL == 0) ? g_xlo : (SEL == 1) ? g_wqlo : g_wplo;
    int i = blockIdx.x * 256 + threadIdx.x;
    if (i >= n4) return;
    float4 v = ((const float4*)src)[i];
    u32 h0, l0, h1, l1;
    split2(v.x, v.y, h0, l0);
    split2(v.z, v.w, h1, l1);
    ((uint2*)hi)[i] = make_uint2(h0, h1);
    ((uint2*)lo)[i] = make_uint2(l0, l1);
}

// ---------------------------------------------------------------------------
// Tensor-core GEMM (mma.sync bf16, hi/lo split), C = A(m,k) * B(n,k)^T, K=384
// MODE 0: A = x(hi/lo), B = w_qkv -> scatter-transpose into g_qkvT
// MODE 1: A = y(hi/lo), B = w_proj -> +bias, row-major out
// CTA tile 128x128, BK=16, 24 k-iters, 3-stage cp.async, 1 barrier/iter
// ---------------------------------------------------------------------------
#define GEMM_SMEM 49152   // 3 stages * 16KB  (also covers epilogue T 34816)

template<int MODE>
__global__ void __launch_bounds__(256, 1)
k_gemm(const float* __restrict__ bias, float* __restrict__ outp)
{
    extern __shared__ char smem[];
    const u32 sb = s2u(smem);
    const int tid  = threadIdx.x;
    const int lane = tid & 31, wid = tid >> 5;
    const int wm = wid & 1, wn = wid >> 1;          // warp grid 2m x 4n
    const int row0 = blockIdx.y * 128;
    const int col0 = blockIdx.x * 128;

    const __nv_bfloat16* Ahi = (MODE == 0) ? g_xhi  : g_yhi;
    const __nv_bfloat16* Alo = (MODE == 0) ? g_xlo  : g_ylo;
    const __nv_bfloat16* Bhi = (MODE == 0) ? g_wqhi : g_wphi;
    const __nv_bfloat16* Blo = (MODE == 0) ? g_wqlo : g_wplo;

    float acc[4][4][4];
#pragma unroll
    for (int a = 0; a < 4; a++)
#pragma unroll
        for (int b = 0; b < 4; b++)
#pragma unroll
            for (int c = 0; c < 4; c++) acc[a][b][c] = 0.f;

    // cp.async: per stage = 4 sub-tiles (Ahi,Alo,Bhi,Blo) of 128 rows x 16 bf16
    const int crow = tid >> 1;
    const int cch  = tid & 1;
    const int cphys = cch ^ ((crow >> 2) & 1);
    const u32 cso = crow * 32 + cphys * 16;
    const size_t gra = (size_t)(row0 + crow) * C_ + cch * 8;
    const size_t grb = (size_t)(col0 + crow) * C_ + cch * 8;

    auto load_tile = [&](int it, int s) {
        const u32 st = sb + s * 16384;
        const int k0 = it * 16;
        cp16(st +     0 + cso, Ahi + gra + k0);
        cp16(st +  4096 + cso, Alo + gra + k0);
        cp16(st +  8192 + cso, Bhi + grb + k0);
        cp16(st + 12288 + cso, Blo + grb + k0);
    };

    // ldmatrix.x4 address for 16-row group starting at r (row stride 32B)
    const int fr_off = (lane & 7) + ((lane >> 3) & 1) * 8;
    const int fr_ch  = lane >> 4;
    auto frag_addr = [&](u32 base, int r) -> u32 {
        int row = r + fr_off;
        int phys = fr_ch ^ ((row >> 2) & 1);
        return base + row * 32 + phys * 16;
    };

    auto compute = [&](int s) {
        const u32 st = sb + s * 16384;
        u32 ah[4][4], al[4][4], bh[2][4], bl[2][4];
        // frags for term 0 first
#pragma unroll
        for (int mt = 0; mt < 4; mt++)
            ldsm4(ah[mt], frag_addr(st + 0, wm * 64 + mt * 16));
#pragma unroll
        for (int np = 0; np < 2; np++)
            ldsm4(bh[np], frag_addr(st + 8192, wn * 32 + np * 16));
        // term 0: Ahi * Bhi  (16 independent accumulators)
#pragma unroll
        for (int mt = 0; mt < 4; mt++)
#pragma unroll
            for (int np = 0; np < 2; np++)
#pragma unroll
                for (int sub = 0; sub < 2; sub++)
                    mma_bf16(acc[mt][np * 2 + sub], ah[mt], bh[np][sub], bh[np][sub + 2]);
        // frags for terms 1-2 (latency hidden behind term 0)
#pragma unroll
        for (int np = 0; np < 2; np++)
            ldsm4(bl[np], frag_addr(st + 12288, wn * 32 + np * 16));
#pragma unroll
        for (int mt = 0; mt < 4; mt++)
            ldsm4(al[mt], frag_addr(st + 4096, wm * 64 + mt * 16));
        // term 1: Ahi * Blo
#pragma unroll
        for (int mt = 0; mt < 4; mt++)
#pragma unroll
            for (int np = 0; np < 2; np++)
#pragma unroll
                for (int sub = 0; sub < 2; sub++)
                    mma_bf16(acc[mt][np * 2 + sub], ah[mt], bl[np][sub], bl[np][sub + 2]);
        // term 2: Alo * Bhi
#pragma unroll
        for (int mt = 0; mt < 4; mt++)
#pragma unroll
            for (int np = 0; np < 2; np++)
#pragma unroll
                for (int sub = 0; sub < 2; sub++)
                    mma_bf16(acc[mt][np * 2 + sub], al[mt], bh[np][sub], bh[np][sub + 2]);
    };

    load_tile(0, 0);
    asm volatile("cp.async.commit_group;" ::: "memory");
    load_tile(1, 1);
    asm volatile("cp.async.commit_group;" ::: "memory");

#pragma unroll 1
    for (int it = 0; it < 24; it++) {
        if (it < 23) {
            asm volatile("cp.async.wait_group 1;" ::: "memory");
        } else {
            asm volatile("cp.async.wait_group 0;" ::: "memory");
        }
        __syncthreads();   // stage `it` visible to all; prior compute retired
        if (it + 2 < 24) {
            load_tile(it + 2, (it + 2) % 3);   // overwrites stage (it-1): safe
            asm volatile("cp.async.commit_group;" ::: "memory");
        }
        compute(it % 3);
    }

    // Epilogue: stage halves through smem T[128][68] for coalesced stores
    float* T = (float*)smem;
    const int g = lane >> 2, tq = lane & 3;
#pragma unroll 1
    for (int jh = 0; jh < 2; jh++) {
        __syncthreads();
        if (MODE == 0) {
            if (wm == jh) {
#pragma unroll
                for (int mt = 0; mt < 4; mt++)
#pragma unroll
                    for (int nt = 0; nt < 4; nt++) {
                        int ml = mt * 16 + g;
                        int nl = wn * 32 + nt * 8 + tq * 2;
#pragma unroll
                        for (int rr = 0; rr < 4; rr++)
                            T[(nl + (rr & 1)) * 68 + ml + (rr >> 1) * 8] = acc[mt][nt][rr];
                    }
            }
        } else {
            if ((wn >> 1) == jh) {
#pragma unroll
                for (int mt = 0; mt < 4; mt++)
#pragma unroll
                    for (int nt = 0; nt < 4; nt++) {
                        int ml = wm * 64 + mt * 16 + g;
                        int nl = (wn & 1) * 32 + nt * 8 + tq * 2;
#pragma unroll
                        for (int rr = 0; rr < 4; rr++)
                            T[(ml + (rr >> 1) * 8) * 68 + nl + (rr & 1)] = acc[mt][nt][rr];
                    }
            }
        }
        __syncthreads();
        if (MODE == 0) {
            const int bb = row0 >> 13;
            const int n0 = (row0 & (N_ - 1)) + jh * 64;
            const int which = col0 / C_;
            const int ccb = col0 - which * C_;
#pragma unroll
            for (int t = 0; t < 8; t++) {
                int fid = tid + t * 256;
                int i = fid >> 4;
                int j = (fid & 15) * 4;
                float4 v = *(float4*)&T[i * 68 + j];
                *(float4*)(g_qkvT + ((size_t)(which * 3072 + bb * C_ + ccb + i)) * N_ + n0 + j) = v;
            }
        } else {
            const int c0 = col0 + jh * 64;
#pragma unroll
            for (int t = 0; t < 8; t++) {
                int fid = tid + t * 256;
                int i = fid >> 4;
                int j = (fid & 15) * 4;
                float4 v = *(float4*)&T[i * 68 + j];
                float4 bv = *(const float4*)(bias + c0 + j);
                v.x += bv.x; v.y += bv.y; v.z += bv.z; v.w += bv.w;
                *(float4*)(outp + (size_t)(row0 + i) * C_ + c0 + j) = v;
            }
        }
    }
}

// ---------------------------------------------------------------------------
// K2a: reciprocal L2 norms of q and k rows
// ---------------------------------------------------------------------------
__global__ void k_norms()
{
    const int idx = blockIdx.x;
    const float4* row = (const float4*)(g_qkvT + (size_t)idx * N_);
    float s = 0.f;
    for (int i = threadIdx.x; i < N_ / 4; i += 256) {
        float4 v = row[i];
        s += v.x * v.x + v.y * v.y + v.z * v.z + v.w * v.w;
    }
    __shared__ float red[256];
    red[threadIdx.x] = s;
    __syncthreads();
    for (int off = 128; off > 0; off >>= 1) {
        if (threadIdx.x < off) red[threadIdx.x] += red[threadIdx.x + off];
        __syncthreads();
    }
    if (threadIdx.x == 0)
        g_rn[idx] = 1.0f / fmaxf(sqrtf(red[0]), 1e-12f);
}

// ---------------------------------------------------------------------------
// K2b: Gram partials
// ---------------------------------------------------------------------------
__global__ void k_logits()
{
    const int chunk = blockIdx.x;
    const int bh    = blockIdx.y;
    const int tid   = threadIdx.x;
    __shared__ float Qs[32][49];
    __shared__ float Ks[32][49];

    const int td = (tid >> 4) * 3;
    const int te = (tid & 15) * 3;
    float acc[3][3] = {};

    const size_t qbase = (size_t)(bh * 48) * N_ + (size_t)chunk * 1024;
    const size_t kbase = qbase + (size_t)3072 * N_;

    for (int t = 0; t < 1024; t += 32) {
#pragma unroll
        for (int it = 0; it < 3; it++) {
            int id  = tid + it * 256;
            int isK = (id >= 384);
            int lidx = id - isK * 384;
            int d = lidx >> 3;
            int nseg = (lidx & 7) * 4;
            size_t base = isK ? kbase : qbase;
            float4 v = *(const float4*)(g_qkvT + base + (size_t)d * N_ + t + nseg);
            float (*S)[49] = isK ? Ks : Qs;
            S[nseg + 0][d] = v.x; S[nseg + 1][d] = v.y;
            S[nseg + 2][d] = v.z; S[nseg + 3][d] = v.w;
        }
        __syncthreads();
#pragma unroll
        for (int kk = 0; kk < 32; kk++) {
            float q0 = Qs[kk][td], q1 = Qs[kk][td + 1], q2 = Qs[kk][td + 2];
            float p0 = Ks[kk][te], p1 = Ks[kk][te + 1], p2 = Ks[kk][te + 2];
            acc[0][0] += q0 * p0; acc[0][1] += q0 * p1; acc[0][2] += q0 * p2;
            acc[1][0] += q1 * p0; acc[1][1] += q1 * p1; acc[1][2] += q1 * p2;
            acc[2][0] += q2 * p0; acc[2][1] += q2 * p1; acc[2][2] += q2 * p2;
        }
        __syncthreads();
    }

    float* outp = g_Spart + ((size_t)chunk * 64 + bh) * 2304;
#pragma unroll
    for (int i = 0; i < 3; i++)
#pragma unroll
        for (int j = 0; j < 3; j++)
            outp[(td + i) * 48 + (te + j)] = acc[i][j];
}

// ---------------------------------------------------------------------------
// K2c: softmax
// ---------------------------------------------------------------------------
__global__ void k_softmax()
{
    const int bh = blockIdx.x;
    const int d  = threadIdx.x;
    if (d >= 48) return;
    const float rq = g_rn[bh * 48 + d];
    const float* rk = g_rn + 3072 + bh * 48;

    float vals[48];
    float mx = -1e30f;
#pragma unroll
    for (int e = 0; e < 48; e++) {
        float s = 0.f;
#pragma unroll
        for (int c = 0; c < 8; c++)
            s += g_Spart[((size_t)c * 64 + bh) * 2304 + d * 48 + e];
        float v = s * rq * rk[e];
        vals[e] = v;
        mx = fmaxf(mx, v);
    }
    float sum = 0.f;
#pragma unroll
    for (int e = 0; e < 48; e++) {
        vals[e] = expf(vals[e] - mx);
        sum += vals[e];
    }
    float inv = 1.0f / sum;
#pragma unroll
    for (int e = 0; e < 48; e++)
        g_attnT[(size_t)bh * 2304 + e * 48 + d] = vals[e] * inv;
}

// ---------------------------------------------------------------------------
// K2d: y = attn @ v, emitted as bf16 hi/lo, row-major [m][j] for K3
// ---------------------------------------------------------------------------
__global__ void k_av()
{
    const int chunk = blockIdx.x;     // 0..31 (256 n each)
    const int bh    = blockIdx.y;
    const int tid   = threadIdx.x;
    __shared__ __align__(16) float At[2304];   // At[e*48 + d]
#pragma unroll
    for (int i = 0; i < 9; i++)
        At[tid + i * 256] = g_attnT[(size_t)bh * 2304 + tid + i * 256];
    __syncthreads();

    const int n = chunk * 256 + tid;
    const size_t vbase = ((size_t)(2 * 3072 + bh * 48)) * N_ + n;
    u64 acc2[24];
#pragma unroll
    for (int i = 0; i < 24; i++) acc2[i] = 0ULL;

#pragma unroll 4
    for (int e = 0; e < 48; e++) {
        float vv = g_qkvT[vbase + (size_t)e * N_];
        u64 vp = pk2(vv, vv);
        const ulonglong2* arow = (const ulonglong2*)&At[e * 48];
#pragma unroll
        for (int t = 0; t < 12; t++) {
            ulonglong2 a2 = arow[t];
            FMA2(acc2[2 * t + 0], a2.x, vp);
            FMA2(acc2[2 * t + 1], a2.y, vp);
        }
    }
    const int b = bh >> 3, h = bh & 7;
    const size_t base = ((size_t)(b * N_ + n)) * C_ + h * 48;
    u32* yh = (u32*)(g_yhi + base);
    u32* yl = (u32*)(g_ylo + base);
#pragma unroll
    for (int t = 0; t < 12; t++) {
        float2 f0 = upk(acc2[2 * t + 0]);
        float2 f1 = upk(acc2[2 * t + 1]);
        u32 h0, l0, h1, l1;
        split2(f0.x, f0.y, h0, l0);
        split2(f1.x, f1.y, h1, l1);
        yh[2 * t + 0] = h0; yh[2 * t + 1] = h1;
        yl[2 * t + 0] = l0; yl[2 * t + 1] = l1;
    }
}

// ---------------------------------------------------------------------------
extern "C" void kernel_launch(void* const* d_in, const int* in_sizes, int n_in,
                              void* d_out, int out_size)
{
    const float* x      = (const float*)d_in[0];
    const float* w_qkv  = (const float*)d_in[1];
    const float* w_proj = (const float*)d_in[2];
    const float* b_proj = (const float*)d_in[3];
    float* out = (float*)d_out;

    const int n4x = M_ * C_ / 4;
    const int n4q = QKVC * C_ / 4;
    const int n4p = C_ * C_ / 4;
    k_split<0><<<(n4x + 255) / 256, 256>>>(x, n4x);
    k_split<1><<<(n4q + 255) / 256, 256>>>(w_qkv, n4q);
    k_split<2><<<(n4p + 255) / 256, 256>>>(w_proj, n4p);

    dim3 g1(QKVC / 128, M_ / 128);        // 9 x 512
    k_gemm<0><<<g1, 256, GEMM_SMEM>>>(nullptr, nullptr);

    k_norms<<<6144, 256>>>();

    dim3 g2(8, 64);
    k_logits<<<g2, 256>>>();

    k_softmax<<<64, 48>>>();

    dim3 g3(32, 64);
    k_av<<<g3, 256>>>();

    dim3 g4(C_ / 128, M_ / 128);          // 3 x 512
    k_gemm<1><<<g4, 256, GEMM_SMEM>>>(b_proj, out);
}